// round 6
// baseline (speedup 1.0000x reference)
#include <cuda_runtime.h>
#include <cstdint>

// Problem constants
#define S_LEN   64
#define D_MODEL 768
#define D_FFN   3072
#define RANK    16
#define MOD_SCALE 0.1f

// Packed f32x2 ops (ptxas won't auto-fuse from C++).
#define FMA_F32X2(d, a, b, c) \
    asm("fma.rn.f32x2 %0, %1, %2, %3;" : "=l"(d) : "l"(a), "l"(b), "l"(c))
#define ADD_F32X2(d, a, b) \
    asm("add.rn.f32x2 %0, %1, %2;" : "=l"(d) : "l"(a), "l"(b))
// Duplicate a scalar float into a packed {s,s} 64-bit operand.
#define DUP_F32X2(d, s) \
    asm("mov.b64 %0, {%1, %1};" : "=l"(d) : "r"(__float_as_uint(s)))

// Scratch for modulation (64 x 16) — device global, no allocation.
__device__ float g_mod[S_LEN * RANK];

// ---------------------------------------------------------------------------
// Kernel 1: modulation[s][r] = 0.1 * tanh( sum_d attn[s][d] * A[d][r] )
// ---------------------------------------------------------------------------
__global__ __launch_bounds__(256)
void mod_kernel(const float* __restrict__ attn,
                const float* __restrict__ A)
{
    const int s     = blockIdx.x;
    const int r     = threadIdx.x & 15;
    const int chunk = threadIdx.x >> 4;          // 0..15
    const int d0    = chunk * (D_MODEL / 16);    // 48 d per chunk

    const float* arow = attn + (size_t)s * D_MODEL;
    float acc = 0.0f;
#pragma unroll 4
    for (int d = d0; d < d0 + (D_MODEL / 16); d++) {
        acc += arow[d] * A[d * RANK + r];
    }

    __shared__ float part[16][RANK];
    part[chunk][r] = acc;
    __syncthreads();

    if (threadIdx.x < RANK) {
        float t = 0.0f;
#pragma unroll
        for (int c = 0; c < 16; c++) t += part[c][threadIdx.x];
        g_mod[s * RANK + threadIdx.x] = MOD_SCALE * tanhf(t);
    }
}

// ---------------------------------------------------------------------------
// Kernel 2: delta_w[p][f] = sum_r C[p][r] * B[r][f],  p = s*768 + d,
//           C[p][r] = mod[s][r] * A[d][r]
//
// R5 structure (non-dup C in smem, mov.b64 dup, packed FFMA2, streaming
// STG.128, 3 CTAs/SM) with latency fixes:
//  - FOUR independent packed accumulator chains (even/odd quads per output
//    half): serial FMA dependency per pair drops 64 -> 32 cycles.
//  - PAIRS_PER_B = 128: halves the number of block prologues
//    (Breg L2 loads + C build + syncthreads).
// ---------------------------------------------------------------------------
#define FTILE       1024
#define PAIRS_PER_B 128
#define THREADS     256

__global__ __launch_bounds__(THREADS, 3)
void deltaw_kernel(const float* __restrict__ A,
                   const float* __restrict__ B,
                   float* __restrict__ out)
{
    const int f0    = blockIdx.y * FTILE + threadIdx.x * 4;
    const int pair0 = blockIdx.x * PAIRS_PER_B;

    // B slab in registers as packed f32x2 halves.
    ulonglong2 Breg[RANK];
#pragma unroll
    for (int r = 0; r < RANK; r++) {
        Breg[r] = *reinterpret_cast<const ulonglong2*>(&B[r * D_FFN + f0]);
    }

    // C non-duplicated: Cs[p][r] = mod[s][r] * A[d][r].
    __shared__ float Cs[PAIRS_PER_B][RANK];
    for (int i = threadIdx.x; i < PAIRS_PER_B * RANK; i += THREADS) {
        const int p  = i >> 4;
        const int r  = i & 15;
        const int pd = pair0 + p;
        const int s  = pd / D_MODEL;
        const int d  = pd % D_MODEL;
        Cs[p][r] = g_mod[s * RANK + r] * A[d * RANK + r];
    }
    __syncthreads();

    float* outp = out + (size_t)pair0 * D_FFN + f0;
#pragma unroll 1
    for (int p = 0; p < PAIRS_PER_B; p++) {
        const float4* cp = reinterpret_cast<const float4*>(&Cs[p][0]);
        // Four independent chains: {even quads, odd quads} x {lo half, hi half}
        uint64_t a0e = 0ull, a0o = 0ull;   // accum for {f0, f0+1}
        uint64_t a1e = 0ull, a1o = 0ull;   // accum for {f0+2, f0+3}
#pragma unroll
        for (int i = 0; i < 4; i += 2) {
            const float4 cE = cp[i];       // quad i   (even chain)
            const float4 cO = cp[i + 1];   // quad i+1 (odd chain)
            uint64_t e0, e1, e2, e3, o0, o1, o2, o3;
            DUP_F32X2(e0, cE.x);  DUP_F32X2(o0, cO.x);
            DUP_F32X2(e1, cE.y);  DUP_F32X2(o1, cO.y);
            DUP_F32X2(e2, cE.z);  DUP_F32X2(o2, cO.z);
            DUP_F32X2(e3, cE.w);  DUP_F32X2(o3, cO.w);
            FMA_F32X2(a0e, e0, Breg[4 * i + 0].x, a0e);
            FMA_F32X2(a1e, e0, Breg[4 * i + 0].y, a1e);
            FMA_F32X2(a0o, o0, Breg[4 * i + 4].x, a0o);
            FMA_F32X2(a1o, o0, Breg[4 * i + 4].y, a1o);
            FMA_F32X2(a0e, e1, Breg[4 * i + 1].x, a0e);
            FMA_F32X2(a1e, e1, Breg[4 * i + 1].y, a1e);
            FMA_F32X2(a0o, o1, Breg[4 * i + 5].x, a0o);
            FMA_F32X2(a1o, o1, Breg[4 * i + 5].y, a1o);
            FMA_F32X2(a0e, e2, Breg[4 * i + 2].x, a0e);
            FMA_F32X2(a1e, e2, Breg[4 * i + 2].y, a1e);
            FMA_F32X2(a0o, o2, Breg[4 * i + 6].x, a0o);
            FMA_F32X2(a1o, o2, Breg[4 * i + 6].y, a1o);
            FMA_F32X2(a0e, e3, Breg[4 * i + 3].x, a0e);
            FMA_F32X2(a1e, e3, Breg[4 * i + 3].y, a1e);
            FMA_F32X2(a0o, o3, Breg[4 * i + 7].x, a0o);
            FMA_F32X2(a1o, o3, Breg[4 * i + 7].y, a1o);
        }
        uint64_t a0, a1;
        ADD_F32X2(a0, a0e, a0o);
        ADD_F32X2(a1, a1e, a1o);
        float4 v;
        v.x = __uint_as_float((uint32_t)(a0 & 0xFFFFFFFFull));
        v.y = __uint_as_float((uint32_t)(a0 >> 32));
        v.z = __uint_as_float((uint32_t)(a1 & 0xFFFFFFFFull));
        v.w = __uint_as_float((uint32_t)(a1 >> 32));
        __stcs(reinterpret_cast<float4*>(outp), v);   // streaming store
        outp += D_FFN;
    }
}

// ---------------------------------------------------------------------------
// Launch
// ---------------------------------------------------------------------------
extern "C" void kernel_launch(void* const* d_in, const int* in_sizes, int n_in,
                              void* d_out, int out_size)
{
    const float* attn = (const float*)d_in[0];  // (1, 64, 768)
    const float* A    = (const float*)d_in[1];  // (768, 16)
    const float* B    = (const float*)d_in[2];  // (16, 3072)
    float* out        = (float*)d_out;          // (1, 64, 768, 3072)

    mod_kernel<<<S_LEN, 256>>>(attn, A);

    dim3 grid((S_LEN * D_MODEL) / PAIRS_PER_B,  // 384
              D_FFN / FTILE);                   // 3
    deltaw_kernel<<<grid, THREADS>>>(A, B, out);
}

// round 7
// speedup vs baseline: 1.0723x; 1.0723x over previous
#include <cuda_runtime.h>
#include <cstdint>

// Problem constants
#define S_LEN   64
#define D_MODEL 768
#define D_FFN   3072
#define RANK    16
#define MOD_SCALE 0.1f

// Packed f32x2 ops (ptxas won't auto-fuse from C++).
#define FMA_F32X2(d, a, b, c) \
    asm("fma.rn.f32x2 %0, %1, %2, %3;" : "=l"(d) : "l"(a), "l"(b), "l"(c))
// Duplicate a scalar float into a packed {s,s} 64-bit operand.
#define DUP_F32X2(d, s) \
    asm("mov.b64 %0, {%1, %1};" : "=l"(d) : "r"(__float_as_uint(s)))

// Scratch: modulation (64 x 16) + work-stealing counter. Device globals.
__device__ float g_mod[S_LEN * RANK];
__device__ unsigned int g_ctr;

// ---------------------------------------------------------------------------
// Kernel 1: modulation[s][r] = 0.1 * tanh( sum_d attn[s][d] * A[d][r] )
// Also resets the work-stealing counter (runs before deltaw in stream order,
// so every graph replay starts from a zeroed counter).
// ---------------------------------------------------------------------------
__global__ __launch_bounds__(256)
void mod_kernel(const float* __restrict__ attn,
                const float* __restrict__ A)
{
    if (blockIdx.x == 0 && threadIdx.x == 0) g_ctr = 0u;

    const int s     = blockIdx.x;
    const int r     = threadIdx.x & 15;
    const int chunk = threadIdx.x >> 4;          // 0..15
    const int d0    = chunk * (D_MODEL / 16);    // 48 d per chunk

    const float* arow = attn + (size_t)s * D_MODEL;
    float acc = 0.0f;
#pragma unroll 4
    for (int d = d0; d < d0 + (D_MODEL / 16); d++) {
        acc += arow[d] * A[d * RANK + r];
    }

    __shared__ float part[16][RANK];
    part[chunk][r] = acc;
    __syncthreads();

    if (threadIdx.x < RANK) {
        float t = 0.0f;
#pragma unroll
        for (int c = 0; c < 16; c++) t += part[c][threadIdx.x];
        g_mod[s * RANK + threadIdx.x] = MOD_SCALE * tanhf(t);
    }
}

// ---------------------------------------------------------------------------
// Kernel 2: delta_w[p][f] = sum_r C[p][r] * B[r][f],  p = s*768 + d,
//           C[p][r] = mod[s][r] * A[d][r]
//
// R5 math (non-dup C smem, mov.b64 dup, 2-chain packed FFMA2, streaming
// STG.128) wrapped in a PERSISTENT-CTA work-stealing scheduler:
//  - grid = 444 = 3 CTAs/SM x 148 SMs: exactly one wave, no quantization.
//  - work item = (f-tile, 64-pair chunk); 2304 items claimed by atomicAdd.
//  - idx-major ordering keeps a block in one f-tile for long runs; Breg is
//    reloaded only on f-tile change (~once per block).
// ---------------------------------------------------------------------------
#define FTILE        1024
#define PAIRS_PER_CH 64
#define THREADS      256
#define N_PCHUNK     ((S_LEN * D_MODEL) / PAIRS_PER_CH)   // 768
#define N_ITEMS      (N_PCHUNK * (D_FFN / FTILE))         // 2304
#define GRID_BLOCKS  444

__global__ __launch_bounds__(THREADS, 3)
void deltaw_kernel(const float* __restrict__ A,
                   const float* __restrict__ B,
                   float* __restrict__ out)
{
    __shared__ float    Cs[PAIRS_PER_CH][RANK];
    __shared__ unsigned s_claim;

    ulonglong2 Breg[RANK];
    int prev_ftile = -1;

    for (;;) {
        // Claim next work item. This barrier also fences the previous
        // iteration's compute loop before Cs/s_claim are overwritten.
        __syncthreads();
        if (threadIdx.x == 0) s_claim = atomicAdd(&g_ctr, 1u);
        __syncthreads();
        const unsigned idx = s_claim;
        if (idx >= N_ITEMS) break;

        const int ftile = (int)(idx / N_PCHUNK);          // 0..2
        const int pair0 = (int)(idx % N_PCHUNK) * PAIRS_PER_CH;
        const int f0    = ftile * FTILE + threadIdx.x * 4;

        // Reload B slab only when the f-tile changes.
        if (ftile != prev_ftile) {
            prev_ftile = ftile;
#pragma unroll
            for (int r = 0; r < RANK; r++) {
                Breg[r] = *reinterpret_cast<const ulonglong2*>(&B[r * D_FFN + f0]);
            }
        }

        // Build C (non-duplicated) for this chunk.
        for (int i = threadIdx.x; i < PAIRS_PER_CH * RANK; i += THREADS) {
            const int p  = i >> 4;
            const int r  = i & 15;
            const int pd = pair0 + p;
            const int s  = pd / D_MODEL;
            const int d  = pd % D_MODEL;
            Cs[p][r] = g_mod[s * RANK + r] * A[d * RANK + r];
        }
        __syncthreads();

        float* outp = out + (size_t)pair0 * D_FFN + f0;
#pragma unroll 1
        for (int p = 0; p < PAIRS_PER_CH; p++) {
            const float4* cp = reinterpret_cast<const float4*>(&Cs[p][0]);
            uint64_t a0 = 0ull;   // packed accum for {f0, f0+1}
            uint64_t a1 = 0ull;   // packed accum for {f0+2, f0+3}
#pragma unroll
            for (int i = 0; i < 4; i++) {
                const float4 c4 = cp[i];      // one broadcast LDS.128
                uint64_t d0, d1, d2, d3;
                DUP_F32X2(d0, c4.x);
                DUP_F32X2(d1, c4.y);
                DUP_F32X2(d2, c4.z);
                DUP_F32X2(d3, c4.w);
                FMA_F32X2(a0, d0, Breg[4 * i + 0].x, a0);
                FMA_F32X2(a1, d0, Breg[4 * i + 0].y, a1);
                FMA_F32X2(a0, d1, Breg[4 * i + 1].x, a0);
                FMA_F32X2(a1, d1, Breg[4 * i + 1].y, a1);
                FMA_F32X2(a0, d2, Breg[4 * i + 2].x, a0);
                FMA_F32X2(a1, d2, Breg[4 * i + 2].y, a1);
                FMA_F32X2(a0, d3, Breg[4 * i + 3].x, a0);
                FMA_F32X2(a1, d3, Breg[4 * i + 3].y, a1);
            }
            float4 v;
            v.x = __uint_as_float((uint32_t)(a0 & 0xFFFFFFFFull));
            v.y = __uint_as_float((uint32_t)(a0 >> 32));
            v.z = __uint_as_float((uint32_t)(a1 & 0xFFFFFFFFull));
            v.w = __uint_as_float((uint32_t)(a1 >> 32));
            __stcs(reinterpret_cast<float4*>(outp), v);   // streaming store
            outp += D_FFN;
        }
    }
}

// ---------------------------------------------------------------------------
// Launch
// ---------------------------------------------------------------------------
extern "C" void kernel_launch(void* const* d_in, const int* in_sizes, int n_in,
                              void* d_out, int out_size)
{
    const float* attn = (const float*)d_in[0];  // (1, 64, 768)
    const float* A    = (const float*)d_in[1];  // (768, 16)
    const float* B    = (const float*)d_in[2];  // (16, 3072)
    float* out        = (float*)d_out;          // (1, 64, 768, 3072)

    mod_kernel<<<S_LEN, 256>>>(attn, A);
    deltaw_kernel<<<GRID_BLOCKS, THREADS>>>(A, B, out);
}